// round 11
// baseline (speedup 1.0000x reference)
#include <cuda_runtime.h>

// Problem constants (match reference)
#define KK   16
#define YY   32
#define CC   16
#define SEGS (KK * YY)          // 512 composite bins
#define BINS (SEGS * CC)        // 8192 fp32 accumulators per replica
#define REPL 32                 // replicated scratch copies (per-warp assignment)
#define EPSV 1e-8f

#define GRID_CTAS 296           // 148 SMs x 2 CTAs of 1024 = one resident wave
#define FOLD_CTAS 16            // last 16 tickets fold one k-slice each

// Scratch: 32 * 8192 * 4B = 1 MB. Zero at module load; the fold phase
// restores it to zero every call (replay-safe).
// Layout within a replica: [seg][sub] — a quad's 4 RED.128s write one
// CONTIGUOUS 64B segment row (load-bearing: keeps L1tex wavefronts per
// RED.E.128 at ~8; both scatter variants tried cost +55us). Do not change.
__device__ float g_scratch[REPL * BINS];

// Ticket counters for the fused tail. Reset protocol: each folding CTA bumps
// g_done after finishing; the one that sees g_done==FOLD_CTAS-1 resets both.
// No spinner can observe a reset mid-wait (resets happen only after every
// folding CTA has exited its spin), so replays are deadlock-free.
__device__ unsigned int g_ticket;
__device__ unsigned int g_done;

// ---------------------------------------------------------------------------
// Single fused kernel.
// Phase 1 (all 296 CTAs): quad-lane streaming scatter-accumulate (~66us,
//   at the shared LTS read+atomic throughput floor; 16.8M RED.E.128).
// Phase 2 (last 16 CTAs to arrive): spin till all arrived, then fold one
//   k-slice: 32-replica reduce + re-zero + eps + Y-normalize (~3us).
// ---------------------------------------------------------------------------
__global__ void __launch_bounds__(1024)
fused_kernel(const int* __restrict__ x_labels,
             const int* __restrict__ y_labels,
             const float4* __restrict__ post,   // float4 view of [N,16]
             float* __restrict__ out,
             int nrows) {
    // ---------------- Phase 1: accumulate ----------------
    {
        const int tid  = blockIdx.x * blockDim.x + threadIdx.x;
        const int lane = threadIdx.x & 31;
        const int sub  = lane & 3;                   // which float4 of the row

        float* replica = g_scratch + ((tid >> 5) & (REPL - 1)) * BINS;
        const int rowstride = (gridDim.x * blockDim.x) >> 2;

#pragma unroll 8
        for (int row = tid >> 2; row < nrows; row += rowstride) {
            int seg = 0;
            if (sub == 0) seg = __ldcs(x_labels + row) * YY + __ldcs(y_labels + row);
            seg = __shfl_sync(0xffffffffu, seg, lane & ~3);

            float4 v = __ldcs(post + (size_t)row * 4 + sub);
            float4* dst = reinterpret_cast<float4*>(replica + seg * CC + sub * 4);
            atomicAdd(dst, v);   // RED.E.128, no return
        }
    }

    // ---------------- Ticket arrival ----------------
    __threadfence();             // make this thread's REDs globally visible
    __syncthreads();             // all threads of the CTA fenced

    __shared__ unsigned int s_ticket;
    if (threadIdx.x == 0) s_ticket = atomicAdd(&g_ticket, 1u);
    __syncthreads();
    const unsigned int ticket = s_ticket;

    if (ticket < GRID_CTAS - FOLD_CTAS) return;      // 280 CTAs exit

    // ---------------- Phase 2: fold (16 CTAs) ----------------
    if (threadIdx.x == 0) {
        // wait until every CTA has arrived (arrivals are unconditional)
        while (*(volatile unsigned int*)&g_ticket != GRID_CTAS) { }
    }
    __syncthreads();
    __threadfence();             // acquire: order scratch reads after arrivals

    const int k = (int)ticket - (GRID_CTAS - FOLD_CTAS);   // 0..15

    __shared__ float4 s_part[1024];      // [chunk(8)][bin4(128)]
    const int t    = threadIdx.x;        // 0..1023
    const int bin4 = t & 127;            // which float4 of the k-slice
    const int rch  = t >> 7;             // replica chunk 0..7

    float4* base = reinterpret_cast<float4*>(g_scratch) + k * 128 + bin4;
    const float4 zero = make_float4(0.f, 0.f, 0.f, 0.f);

    float4 acc = zero;
#pragma unroll
    for (int r = 0; r < 4; r++) {
        float4* p = base + (rch * 4 + r) * (BINS / 4);   // stride 32KB
        float4 v = *p;
        *p = zero;                        // restore scratch for next replay
        acc.x += v.x; acc.y += v.y; acc.z += v.z; acc.w += v.w;
    }
    s_part[rch * 128 + bin4] = acc;
    __syncthreads();

#pragma unroll
    for (int step = 4; step >= 1; step >>= 1) {
        if (rch < step) {
            float4 a = s_part[rch * 128 + bin4];
            float4 b = s_part[(rch + step) * 128 + bin4];
            a.x += b.x; a.y += b.y; a.z += b.z; a.w += b.w;
            s_part[rch * 128 + bin4] = a;
        }
        __syncthreads();
    }

    if (t < 128) {
        float4 num = s_part[bin4];
        num.x += EPSV; num.y += EPSV; num.z += EPSV; num.w += EPSV;
        s_part[bin4] = num;
    }
    __syncthreads();
    if (t < 128) {
        const int sub = bin4 & 3;        // float4 chunk within a segment
        float4 num = s_part[bin4];
        float4 den = make_float4(0.f, 0.f, 0.f, 0.f);
#pragma unroll
        for (int yy = 0; yy < YY; yy++) {
            float4 v = s_part[yy * 4 + sub];
            den.x += v.x; den.y += v.y; den.z += v.z; den.w += v.w;
        }
        float4 r;
        r.x = num.x / den.x; r.y = num.y / den.y;
        r.z = num.z / den.z; r.w = num.w / den.w;
        reinterpret_cast<float4*>(out)[k * 128 + bin4] = r;
    }

    // ---------------- Counter reset (replay safety) ----------------
    __syncthreads();
    if (t == 0) {
        __threadfence();
        unsigned int d = atomicAdd(&g_done, 1u);
        if (d == FOLD_CTAS - 1) {        // last folding CTA: everyone else
            g_done   = 0u;               // has exited its spin already
            g_ticket = 0u;
            __threadfence();
        }
    }
}

// ---------------------------------------------------------------------------
// Launch — ONE node.
// ---------------------------------------------------------------------------
extern "C" void kernel_launch(void* const* d_in, const int* in_sizes, int n_in,
                              void* d_out, int out_size) {
    const int*    x_labels = (const int*)d_in[0];
    const int*    y_labels = (const int*)d_in[1];
    const float4* post     = (const float4*)d_in[2];
    float*        out      = (float*)d_out;

    const int nrows = in_sizes[0];      // N = 4194304

    fused_kernel<<<GRID_CTAS, 1024>>>(x_labels, y_labels, post, out, nrows);
}

// round 12
// speedup vs baseline: 1.1658x; 1.1658x over previous
#include <cuda_runtime.h>

// Problem constants (match reference)
#define KK   16
#define YY   32
#define CC   16
#define SEGS (KK * YY)          // 512 composite bins
#define BINS (SEGS * CC)        // 8192 fp32 accumulators per replica
#define REPL 32                 // replicated scratch copies (per-warp assignment)
#define EPSV 1e-8f

// Scratch: 32 * 8192 * 4B = 1 MB. Zero at module load; finalize restores it
// to zero every call (replay-safe).
// Layout within a replica: [seg][sub] — a quad's 4 RED.128s write one
// CONTIGUOUS 64B segment row (load-bearing; scatter variants cost +55us).
__device__ float g_scratch[REPL * BINS];

// ---------------------------------------------------------------------------
// Kernel 1: streaming scatter-accumulate — quad-lane scheme, HIGH-REG build.
// R11's ncu (first real profile of this phase) showed nothing saturated
// (DRAM 36%, L2 39%, issue 11%) => latency-bound, not throughput-bound.
// The 32-reg cap there collapsed MLP. Here: __launch_bounds__(256, 4)
// gives ptxas a 64-reg budget so the unroll-8 body can keep 8 independent
// LDG.128 (+ their REDs) in flight per thread. 4 CTAs/SM x 256 thr =
// 1024 thr/SM; outstanding bytes/SM ~ 1024*8*16B = 128KB >> BW*latency
// share, so the halved occupancy is covered by doubled per-thread MLP.
// Grid = 592 = 148 SMs x 4 CTAs: exactly one resident wave.
// ---------------------------------------------------------------------------
__global__ void __launch_bounds__(256, 4)
accum_kernel(const int* __restrict__ x_labels,
             const int* __restrict__ y_labels,
             const float4* __restrict__ post,   // float4 view of [N,16]
             int nrows) {
    const int tid  = blockIdx.x * blockDim.x + threadIdx.x;
    const int lane = threadIdx.x & 31;
    const int sub  = lane & 3;                       // which float4 of the row

    // per-warp replica: consecutive warps hit different 32KB scratch regions
    float* replica = g_scratch + ((tid >> 5) & (REPL - 1)) * BINS;

    const int rowstride = (gridDim.x * blockDim.x) >> 2;

#pragma unroll 8
    for (int row = tid >> 2; row < nrows; row += rowstride) {
        int seg = 0;
        if (sub == 0) seg = __ldcs(x_labels + row) * YY + __ldcs(y_labels + row);
        seg = __shfl_sync(0xffffffffu, seg, lane & ~3);

        float4 v = __ldcs(post + (size_t)row * 4 + sub);
        float4* dst = reinterpret_cast<float4*>(replica + seg * CC + sub * 4);
        atomicAdd(dst, v);   // sm_90+ vector atomic -> RED.E.128 (no return)
    }
}

// ---------------------------------------------------------------------------
// Kernel 2: fold replicas + RE-ZERO scratch + add eps + normalize over Y.
// (Proven R8 epilogue, unchanged.) Grid = 16 blocks (one per k), 1024 thr.
// ---------------------------------------------------------------------------
__global__ void finalize_kernel(float* __restrict__ out) {
    __shared__ float4 s_part[1024];      // [chunk(8)][bin4(128)]

    const int k    = blockIdx.x;         // 0..15
    const int t    = threadIdx.x;        // 0..1023
    const int bin4 = t & 127;            // which float4 of the k-slice
    const int rch  = t >> 7;             // replica chunk 0..7

    float4* base = reinterpret_cast<float4*>(g_scratch) + k * 128 + bin4;
    const float4 zero = make_float4(0.f, 0.f, 0.f, 0.f);

    float4 acc = zero;
#pragma unroll
    for (int r = 0; r < 4; r++) {
        float4* p = base + (rch * 4 + r) * (BINS / 4);   // stride 32KB
        float4 v = *p;
        *p = zero;                        // restore for next replay
        acc.x += v.x; acc.y += v.y; acc.z += v.z; acc.w += v.w;
    }
    s_part[rch * 128 + bin4] = acc;
    __syncthreads();

#pragma unroll
    for (int step = 4; step >= 1; step >>= 1) {
        if (rch < step) {
            float4 a = s_part[rch * 128 + bin4];
            float4 b = s_part[(rch + step) * 128 + bin4];
            a.x += b.x; a.y += b.y; a.z += b.z; a.w += b.w;
            s_part[rch * 128 + bin4] = a;
        }
        __syncthreads();
    }

    if (t < 128) {
        float4 num = s_part[bin4];
        num.x += EPSV; num.y += EPSV; num.z += EPSV; num.w += EPSV;
        s_part[bin4] = num;
    }
    __syncthreads();
    if (t < 128) {
        const int sub = bin4 & 3;        // float4 chunk within a segment
        float4 num = s_part[bin4];
        float4 den = make_float4(0.f, 0.f, 0.f, 0.f);
#pragma unroll
        for (int yy = 0; yy < YY; yy++) {
            float4 v = s_part[yy * 4 + sub];
            den.x += v.x; den.y += v.y; den.z += v.z; den.w += v.w;
        }
        float4 r;
        r.x = num.x / den.x; r.y = num.y / den.y;
        r.z = num.z / den.z; r.w = num.w / den.w;
        reinterpret_cast<float4*>(out)[k * 128 + bin4] = r;
    }
}

// ---------------------------------------------------------------------------
// Launch — two nodes.
// ---------------------------------------------------------------------------
extern "C" void kernel_launch(void* const* d_in, const int* in_sizes, int n_in,
                              void* d_out, int out_size) {
    const int*    x_labels = (const int*)d_in[0];
    const int*    y_labels = (const int*)d_in[1];
    const float4* post     = (const float4*)d_in[2];
    float*        out      = (float*)d_out;

    const int nrows = in_sizes[0];      // N = 4194304

    // 592 CTAs x 256 threads = 148 SMs x 4 resident CTAs: single wave,
    // 64-reg budget for MLP.
    accum_kernel<<<592, 256>>>(x_labels, y_labels, post, nrows);

    finalize_kernel<<<KK, 1024>>>(out);
}